// round 16
// baseline (speedup 1.0000x reference)
#include <cuda_runtime.h>
#include <cooperative_groups.h>
namespace cg = cooperative_groups;

#define BATCH 256
#define SEQ 512
#define HID 128
#define GATES 512

// SMEM float offsets (k_lstm). Staging W1/W2x/W2h dead after reg copy; zs overlays W1.
#define OFF_W1   0        // staging 16384
#define OFF_ZS4  0        // overlay: [2 parity][4 quarter][8 row][128 gcol] = 8192
#define OFF_W2X  16384
#define OFF_W2H  32768
#define OFF_H1B  49152    // [2][8][128]
#define OFF_H2B  51200    // [2][8][128]
#define OFF_B2S  53248    // [128]
#define OFF_CM   53376    // 512 bytes
#define SMEM_FLOATS 53504 // 214016 B

__device__ float g_P2[100*GATES];
__device__ __align__(8) unsigned char g_maskT[SEQ*BATCH];
__device__ __align__(8) unsigned char g_idxT[SEQ*BATCH];
__device__ float g_sent[(size_t)BATCH*SEQ*HID];
__device__ float g_beta[BATCH*HID];
__device__ float g_gamma[BATCH*HID];

// fast nonlinearities: MUFU.EX2 + RCP path (~1e-7 per-call rel err)
__device__ __forceinline__ float sigm(float x){ return 1.f/(1.f+__expf(-x)); }
__device__ __forceinline__ float tanh_f(float x){ return 2.f/(1.f+__expf(-2.f*x)) - 1.f; }

// tiled transpose: coalesced reads AND writes
__global__ void __launch_bounds__(256) k_trans(const int* __restrict__ ch, const int* __restrict__ wd){
    __shared__ int tc[32][33];
    __shared__ int tw[32][33];
    int lane = threadIdx.x & 31, row = threadIdx.x >> 5;
    int t0 = blockIdx.x * 32, b0 = blockIdx.y * 32;
    for (int r = row; r < 32; r += 8) {
        tc[r][lane] = ch[(b0 + r) * SEQ + t0 + lane];
        tw[r][lane] = wd[(b0 + r) * SEQ + t0 + lane];
    }
    __syncthreads();
    for (int r = row; r < 32; r += 8) {
        int c = tc[lane][r], w = tw[lane][r];
        g_maskT[(t0 + r) * BATCH + b0 + lane] = (unsigned char)(c == 0);
        g_idxT [(t0 + r) * BATCH + b0 + lane] = (unsigned char)(c * 10 + w);
    }
}

// no-op: shifts the ncu capture slot (-s 5 -c 1) onto k_lstm
__global__ void k_dummy(){}

// one block per (char,word) pair
__global__ void k_table(const float* __restrict__ emb_char,const float* __restrict__ emb_word,
                        const float* __restrict__ Wwc,const float* __restrict__ bwc,
                        const float* __restrict__ l1_Wx,const float* __restrict__ l1_b){
    __shared__ float xv[64];
    int p=blockIdx.x, tid=threadIdx.x; // 100 blocks, 512 threads
    int c=p/10, w=p%10;
    if(tid<64){
        float s=emb_char[c*64+tid]+bwc[tid];
        for(int d=0;d<32;d++) s=fmaf(emb_word[w*32+d],Wwc[d*64+tid],s);
        xv[tid]=s;
    }
    __syncthreads();
    float acc=l1_b[tid];
#pragma unroll 8
    for(int e=0;e<64;e++) acc=fmaf(xv[e],l1_Wx[e*GATES+tid],acc);
    g_P2[p*GATES+tid]=acc;
}

// ===== k_lstm: R13/R15 structure; ONLY change = fast sigm/tanh =====
__global__ void __cluster_dims__(4,1,1) __launch_bounds__(512,1)
k_lstm(const float* __restrict__ Wh1g,const float* __restrict__ Wx2g,
       const float* __restrict__ Wh2g,const float* __restrict__ b2g){
    extern __shared__ float sm[];
    float* W1  = sm + OFF_W1;
    float* W2x = sm + OFF_W2X;
    float* W2h = sm + OFF_W2H;
    float* zs  = sm + OFF_ZS4;
    float* h1b = sm + OFF_H1B;
    float* h2b = sm + OFF_H2B;
    float* b2s = sm + OFF_B2S;
    unsigned char* cmask = (unsigned char*)(sm + OFF_CM);

    const int tid = threadIdx.x, o = blockIdx.x & 3, cl = blockIdx.x >> 2;
    const int j = tid & 127, q = tid >> 7;
    const int rr = (tid >> 5) & 7, ii = tid & 31;
    const int oc = o * 32 + ii;
    const int bb = cl * 8 + rr;

    for (int idx = tid; idx < 128 * 128; idx += 512) {
        int jj = idx & 127, k = idx >> 7;
        int gc = ((jj >> 5) << 7) + o * 32 + (jj & 31);
        int dst = (k >> 2) * 512 + jj * 4 + (k & 3);
        W1 [dst] = Wh1g[k * GATES + gc];
        W2x[dst] = Wx2g[k * GATES + gc];
        W2h[dst] = Wh2g[k * GATES + gc];
    }
    if (tid < 128) b2s[tid] = b2g[(tid >> 5) * 128 + o * 32 + (tid & 31)];
    for (int idx = tid; idx < 2048; idx += 512) { h1b[idx] = 0.f; h2b[idx] = 0.f; }
    for (int s = tid; s < SEQ; s += 512) {
        unsigned long long v = *(const unsigned long long*)(g_maskT + s * BATCH + cl * 8);
        unsigned mm = 0;
#pragma unroll
        for (int r = 0; r < 8; r++) mm |= ((unsigned)((v >> (8 * r)) & 1ull)) << r;
        cmask[s] = (unsigned char)mm;
    }
    __syncthreads();

    float4 w1r[8];
    float4 wtr[16];
    {
        const float* W1p = W1 + q * (8 * 512) + j * 4;
        const float* Wtp = ((q < 2) ? (W2x + (q * 16) * 512)
                                    : (W2h + ((q - 2) * 16) * 512))
                           + j * 4;
#pragma unroll
        for (int kq = 0; kq < 8; kq++)  w1r[kq] = *(const float4*)(W1p + kq * 512);
#pragma unroll
        for (int kq = 0; kq < 16; kq++) wtr[kq] = *(const float4*)(Wtp + kq * 512);
    }
    const float b2r = (q == 0) ? b2s[j] : 0.f;
    __syncthreads();

    cg::cluster_group cluster = cg::this_cluster();
    cluster.sync();

    float c1 = 0.f, c2 = 0.f;
    float h1cur = 0.f, h2cur = 0.f;
    int p = 0;

    for (int t = 0; t < SEQ; t++) {
        const int m = cmask[t];
        if (m == 0) {
            if (tid < 256) g_sent[((size_t)bb * SEQ + t) * HID + oc] = h2cur;
            continue;
        }
        const unsigned long long idx8 = *(const unsigned long long*)(g_idxT + t * BATCH + cl * 8);
        const int pq = p ^ 1;
        float* zq = zs + p * 4096 + q * 1024;

        {
            unsigned mm = (unsigned)m;
            while (mm) {
                int r = __ffs(mm) - 1; mm &= mm - 1;
                const float* hv = h1b + p * 1024 + r * 128 + q * 32;
                float z = 0.f;
#pragma unroll
                for (int kq = 0; kq < 8; kq++) {
                    float4 a4 = *(const float4*)(hv + kq * 4);
                    z = fmaf(a4.x, w1r[kq].x, z); z = fmaf(a4.y, w1r[kq].y, z);
                    z = fmaf(a4.z, w1r[kq].z, z); z = fmaf(a4.w, w1r[kq].w, z);
                }
                if (q == 0)
                    z += g_P2[(int)((idx8 >> (8 * r)) & 255ull) * GATES + ((j >> 5) << 7) + o * 32 + (j & 31)];
                zq[r * 128 + j] = z;
            }
        }
        __syncthreads();

        const bool act = (m >> rr) & 1;
        if (tid < 256) {
            if (act) {
                const float* zp = zs + p * 4096 + rr * 128;
                float zi = zp[ii]      + zp[1024 + ii]      + zp[2048 + ii]      + zp[3072 + ii];
                float zf = zp[32 + ii] + zp[1024 + 32 + ii] + zp[2048 + 32 + ii] + zp[3072 + 32 + ii];
                float zg = zp[64 + ii] + zp[1024 + 64 + ii] + zp[2048 + 64 + ii] + zp[3072 + 64 + ii];
                float zo = zp[96 + ii] + zp[1024 + 96 + ii] + zp[2048 + 96 + ii] + zp[3072 + 96 + ii];
                float cn = sigm(zf) * c1 + sigm(zi) * tanh_f(zg); c1 = cn;
                h1cur = sigm(zo) * tanh_f(cn);
            }
#pragma unroll
            for (int rk = 0; rk < 4; rk++)
                cluster.map_shared_rank(h1b, rk)[pq * 1024 + rr * 128 + oc] = h1cur;
        }
        cluster.sync();

        {
            const float* hbase = (q < 2) ? (h1b + pq * 1024) : (h2b + p * 1024);
            const int koff = (q & 1) * 64;
            unsigned mm = (unsigned)m;
            while (mm) {
                int r = __ffs(mm) - 1; mm &= mm - 1;
                const float* hv = hbase + r * 128 + koff;
                float z = b2r;
#pragma unroll
                for (int kq = 0; kq < 16; kq++) {
                    float4 a4 = *(const float4*)(hv + kq * 4);
                    z = fmaf(a4.x, wtr[kq].x, z); z = fmaf(a4.y, wtr[kq].y, z);
                    z = fmaf(a4.z, wtr[kq].z, z); z = fmaf(a4.w, wtr[kq].w, z);
                }
                zq[r * 128 + j] = z;
            }
        }
        __syncthreads();

        if (tid < 256) {
            if (act) {
                const float* zp = zs + p * 4096 + rr * 128;
                float zi = zp[ii]      + zp[1024 + ii]      + zp[2048 + ii]      + zp[3072 + ii];
                float zf = zp[32 + ii] + zp[1024 + 32 + ii] + zp[2048 + 32 + ii] + zp[3072 + 32 + ii];
                float zg = zp[64 + ii] + zp[1024 + 64 + ii] + zp[2048 + 64 + ii] + zp[3072 + 64 + ii];
                float zo = zp[96 + ii] + zp[1024 + 96 + ii] + zp[2048 + 96 + ii] + zp[3072 + 96 + ii];
                float cn = sigm(zf) * c2 + sigm(zi) * tanh_f(zg); c2 = cn;
                h2cur = sigm(zo) * tanh_f(cn);
            }
#pragma unroll
            for (int rk = 0; rk < 4; rk++)
                cluster.map_shared_rank(h2b, rk)[pq * 1024 + rr * 128 + oc] = h2cur;
            g_sent[((size_t)bb * SEQ + t) * HID + oc] = h2cur;
        }
        p = pq;
    }
    cluster.sync();
}

__global__ void k_subject(const int* __restrict__ subj,
                          const float* __restrict__ betaW,const float* __restrict__ betab,
                          const float* __restrict__ gammaW,const float* __restrict__ gammab){
    __shared__ float sub[256];
    int b = blockIdx.x, tid = threadIdx.x;
    int s0 = subj[b*2+0], s1 = subj[b*2+1];
    if (tid < 128) sub[tid] = g_sent[((size_t)b*SEQ+s0)*HID + tid];
    else           sub[tid] = g_sent[((size_t)b*SEQ+s1)*HID + (tid-128)];
    __syncthreads();
    int col = tid & 127;
    const float* Wm = (tid < 128) ? betaW : gammaW;
    float a = (tid < 128) ? betab[col] : gammab[col];
    for (int k = 0; k < 256; k++) a = fmaf(sub[k], Wm[k*HID + col], a);
    if (tid < 128) g_beta [b*HID + col] = a;
    else           g_gamma[b*HID + col] = a;
}

// k_post v2: poW/pob/subW/subb staged in SMEM once per block (8 rows amortize it)
__global__ void __launch_bounds__(256) k_post(const float* __restrict__ poW,const float* __restrict__ pob,
                                              const float* __restrict__ subW,const float* __restrict__ subb,
                                              float* __restrict__ out){
    __shared__ float rowS[8][132];
    __shared__ float ctxS[8][132];
    __shared__ float poWs[128*20];   // 10240 B
    __shared__ float pobs[20];
    __shared__ float subWs[256];
    __shared__ float subbs[2];
    int tid=threadIdx.x;
    for (int i = tid; i < 128*20; i += 256) poWs[i] = poW[i];
    if (tid < 20)  pobs[tid]  = pob[tid];
    if (tid < 256) subWs[tid] = subW[tid];
    if (tid < 2)   subbs[tid] = subb[tid];

    int warp=tid>>5, lane=tid&31;
    size_t rid=(size_t)blockIdx.x*8+warp;      // b*512+t
    int b=(int)(rid>>9);
    const float* row=g_sent+rid*HID;
    float x0=row[lane], x1=row[lane+32], x2=row[lane+64], x3=row[lane+96];
    float s=x0+x1+x2+x3, q=x0*x0+x1*x1+x2*x2+x3*x3;
#pragma unroll
    for(int d=16;d;d>>=1){ s+=__shfl_xor_sync(0xffffffffu,s,d); q+=__shfl_xor_sync(0xffffffffu,q,d); }
    float u=s*(1.f/128.f);
    float v=fmaxf(q*(1.f/128.f)-u*u,0.f);
    float inv=rsqrtf(v+1e-12f);
    const float* gma=g_gamma+b*HID; const float* bta=g_beta+b*HID;
    rowS[warp][lane]   =x0; ctxS[warp][lane]   =fmaf(gma[lane]   *inv,(x0-u),bta[lane]);
    rowS[warp][lane+32]=x1; ctxS[warp][lane+32]=fmaf(gma[lane+32]*inv,(x1-u),bta[lane+32]);
    rowS[warp][lane+64]=x2; ctxS[warp][lane+64]=fmaf(gma[lane+64]*inv,(x2-u),bta[lane+64]);
    rowS[warp][lane+96]=x3; ctxS[warp][lane+96]=fmaf(gma[lane+96]*inv,(x3-u),bta[lane+96]);
    __syncthreads();   // weights staged + row/ctx visible
    if(lane<20){
        float a0=pobs[lane], a1=0.f, a2=0.f, a3=0.f;
#pragma unroll
        for(int k=0;k<128;k+=4){
            a0=fmaf(ctxS[warp][k  ],poWs[(k  )*20+lane],a0);
            a1=fmaf(ctxS[warp][k+1],poWs[(k+1)*20+lane],a1);
            a2=fmaf(ctxS[warp][k+2],poWs[(k+2)*20+lane],a2);
            a3=fmaf(ctxS[warp][k+3],poWs[(k+3)*20+lane],a3);
        }
        out[(size_t)BATCH*SEQ*2 + rid*20 + lane]=(a0+a1)+(a2+a3);
    }else if(lane<22){
        int c=lane-20;
        float a0=subbs[c], a1=0.f;
#pragma unroll
        for(int k=0;k<128;k+=2){
            a0=fmaf(rowS[warp][k  ],subWs[(k  )*2+c],a0);
            a1=fmaf(rowS[warp][k+1],subWs[(k+1)*2+c],a1);
        }
        out[rid*2+c]=a0+a1;
    }
}

extern "C" void kernel_launch(void* const* d_in, const int* in_sizes, int n_in,
                              void* d_out, int out_size){
    const int*   char_ids=(const int*)d_in[0];
    const int*   word_ids=(const int*)d_in[1];
    const int*   subj    =(const int*)d_in[2];
    const float* emb_char=(const float*)d_in[3];
    const float* emb_word=(const float*)d_in[4];
    const float* Wwc     =(const float*)d_in[5];
    const float* bwc     =(const float*)d_in[6];
    const float* l1_Wx   =(const float*)d_in[7];
    const float* l1_Wh   =(const float*)d_in[8];
    const float* l1_b    =(const float*)d_in[9];
    const float* l2_Wx   =(const float*)d_in[10];
    const float* l2_Wh   =(const float*)d_in[11];
    const float* l2_b    =(const float*)d_in[12];
    const float* beta_W  =(const float*)d_in[13];
    const float* beta_b  =(const float*)d_in[14];
    const float* gamma_W =(const float*)d_in[15];
    const float* gamma_b =(const float*)d_in[16];
    const float* sub_W   =(const float*)d_in[17];
    const float* sub_b   =(const float*)d_in[18];
    const float* po_W    =(const float*)d_in[19];
    const float* po_b    =(const float*)d_in[20];
    float* out=(float*)d_out;

    const int smem_bytes = SMEM_FLOATS * 4; // 214016
    cudaFuncSetAttribute(k_lstm, cudaFuncAttributeMaxDynamicSharedMemorySize, smem_bytes);

    dim3 tgrid(SEQ/32, BATCH/32);
    k_trans<<<tgrid,256>>>(char_ids,word_ids);
    k_table<<<100,512>>>(emb_char,emb_word,Wwc,bwc,l1_Wx,l1_b);
    k_dummy<<<1,32>>>();   // shifts ncu -s 5 capture slot onto k_lstm
    k_lstm<<<128,512,smem_bytes>>>(l1_Wh,l2_Wx,l2_Wh,l2_b);
    k_subject<<<BATCH,256>>>(subj,beta_W,beta_b,gamma_W,gamma_b);
    k_post<<<(BATCH*SEQ)/8,256>>>(po_W,po_b,sub_W,sub_b,out);
}

// round 17
// speedup vs baseline: 1.1609x; 1.1609x over previous
#include <cuda_runtime.h>
#include <cooperative_groups.h>
namespace cg = cooperative_groups;

#define BATCH 256
#define SEQ 512
#define HID 128
#define GATES 512

// SMEM float offsets (k_lstm). Staging W1/W2x/W2h dead after reg copy; zs overlays W1.
#define OFF_W1   0        // staging 16384
#define OFF_ZS4  0        // overlay: [2 parity][4 quarter][8 row][128 gcol] = 8192
#define OFF_W2X  16384
#define OFF_W2H  32768
#define OFF_H1B  49152    // [2][8][128]
#define OFF_H2B  51200    // [2][8][128]
#define OFF_B2S  53248    // [128]
#define OFF_CM   53376    // 512 bytes
#define SMEM_FLOATS 53504 // 214016 B

__device__ float g_P2[100*GATES];
__device__ __align__(8) unsigned char g_maskT[SEQ*BATCH];
__device__ __align__(8) unsigned char g_idxT[SEQ*BATCH];
__device__ float g_sent[(size_t)BATCH*SEQ*HID];
__device__ float g_beta[BATCH*HID];
__device__ float g_gamma[BATCH*HID];

// libdevice tanhf lowers to HW MUFU.TANH on sm_103a — fastest known path (R16 verdict)
__device__ __forceinline__ float sigm(float x){ return 0.5f*tanhf(0.5f*x)+0.5f; }

// tiled transpose: coalesced reads AND writes
__global__ void __launch_bounds__(256) k_trans(const int* __restrict__ ch, const int* __restrict__ wd){
    __shared__ int tc[32][33];
    __shared__ int tw[32][33];
    int lane = threadIdx.x & 31, row = threadIdx.x >> 5;
    int t0 = blockIdx.x * 32, b0 = blockIdx.y * 32;
    for (int r = row; r < 32; r += 8) {
        tc[r][lane] = ch[(b0 + r) * SEQ + t0 + lane];
        tw[r][lane] = wd[(b0 + r) * SEQ + t0 + lane];
    }
    __syncthreads();
    for (int r = row; r < 32; r += 8) {
        int c = tc[lane][r], w = tw[lane][r];
        g_maskT[(t0 + r) * BATCH + b0 + lane] = (unsigned char)(c == 0);
        g_idxT [(t0 + r) * BATCH + b0 + lane] = (unsigned char)(c * 10 + w);
    }
}

// no-op: shifts the ncu capture slot (-s 5 -c 1) onto k_lstm
__global__ void k_dummy(){}

// one block per (char,word) pair
__global__ void k_table(const float* __restrict__ emb_char,const float* __restrict__ emb_word,
                        const float* __restrict__ Wwc,const float* __restrict__ bwc,
                        const float* __restrict__ l1_Wx,const float* __restrict__ l1_b){
    __shared__ float xv[64];
    int p=blockIdx.x, tid=threadIdx.x; // 100 blocks, 512 threads
    int c=p/10, w=p%10;
    if(tid<64){
        float s=emb_char[c*64+tid]+bwc[tid];
        for(int d=0;d<32;d++) s=fmaf(emb_word[w*32+d],Wwc[d*64+tid],s);
        xv[tid]=s;
    }
    __syncthreads();
    float acc=l1_b[tid];
#pragma unroll 8
    for(int e=0;e<64;e++) acc=fmaf(xv[e],l1_Wx[e*GATES+tid],acc);
    g_P2[p*GATES+tid]=acc;
}

// ===== k_lstm: byte-exact R15 (measured 547us, regs=128, no spill) =====
__global__ void __cluster_dims__(4,1,1) __launch_bounds__(512,1)
k_lstm(const float* __restrict__ Wh1g,const float* __restrict__ Wx2g,
       const float* __restrict__ Wh2g,const float* __restrict__ b2g){
    extern __shared__ float sm[];
    float* W1  = sm + OFF_W1;
    float* W2x = sm + OFF_W2X;
    float* W2h = sm + OFF_W2H;
    float* zs  = sm + OFF_ZS4;
    float* h1b = sm + OFF_H1B;
    float* h2b = sm + OFF_H2B;
    float* b2s = sm + OFF_B2S;
    unsigned char* cmask = (unsigned char*)(sm + OFF_CM);

    const int tid = threadIdx.x, o = blockIdx.x & 3, cl = blockIdx.x >> 2;
    const int j = tid & 127, q = tid >> 7;
    const int rr = (tid >> 5) & 7, ii = tid & 31;
    const int oc = o * 32 + ii;
    const int bb = cl * 8 + rr;

    for (int idx = tid; idx < 128 * 128; idx += 512) {
        int jj = idx & 127, k = idx >> 7;
        int gc = ((jj >> 5) << 7) + o * 32 + (jj & 31);
        int dst = (k >> 2) * 512 + jj * 4 + (k & 3);
        W1 [dst] = Wh1g[k * GATES + gc];
        W2x[dst] = Wx2g[k * GATES + gc];
        W2h[dst] = Wh2g[k * GATES + gc];
    }
    if (tid < 128) b2s[tid] = b2g[(tid >> 5) * 128 + o * 32 + (tid & 31)];
    for (int idx = tid; idx < 2048; idx += 512) { h1b[idx] = 0.f; h2b[idx] = 0.f; }
    for (int s = tid; s < SEQ; s += 512) {
        unsigned long long v = *(const unsigned long long*)(g_maskT + s * BATCH + cl * 8);
        unsigned mm = 0;
#pragma unroll
        for (int r = 0; r < 8; r++) mm |= ((unsigned)((v >> (8 * r)) & 1ull)) << r;
        cmask[s] = (unsigned char)mm;
    }
    __syncthreads();

    float4 w1r[8];
    float4 wtr[16];
    {
        const float* W1p = W1 + q * (8 * 512) + j * 4;
        const float* Wtp = ((q < 2) ? (W2x + (q * 16) * 512)
                                    : (W2h + ((q - 2) * 16) * 512))
                           + j * 4;
#pragma unroll
        for (int kq = 0; kq < 8; kq++)  w1r[kq] = *(const float4*)(W1p + kq * 512);
#pragma unroll
        for (int kq = 0; kq < 16; kq++) wtr[kq] = *(const float4*)(Wtp + kq * 512);
    }
    const float b2r = (q == 0) ? b2s[j] : 0.f;
    __syncthreads();

    cg::cluster_group cluster = cg::this_cluster();
    cluster.sync();

    float c1 = 0.f, c2 = 0.f;
    float h1cur = 0.f, h2cur = 0.f;
    int p = 0;

    for (int t = 0; t < SEQ; t++) {
        const int m = cmask[t];
        if (m == 0) {
            if (tid < 256) g_sent[((size_t)bb * SEQ + t) * HID + oc] = h2cur;
            continue;
        }
        const unsigned long long idx8 = *(const unsigned long long*)(g_idxT + t * BATCH + cl * 8);
        const int pq = p ^ 1;
        float* zq = zs + p * 4096 + q * 1024;

        {
            unsigned mm = (unsigned)m;
            while (mm) {
                int r = __ffs(mm) - 1; mm &= mm - 1;
                const float* hv = h1b + p * 1024 + r * 128 + q * 32;
                float z = 0.f;
#pragma unroll
                for (int kq = 0; kq < 8; kq++) {
                    float4 a4 = *(const float4*)(hv + kq * 4);
                    z = fmaf(a4.x, w1r[kq].x, z); z = fmaf(a4.y, w1r[kq].y, z);
                    z = fmaf(a4.z, w1r[kq].z, z); z = fmaf(a4.w, w1r[kq].w, z);
                }
                if (q == 0)
                    z += g_P2[(int)((idx8 >> (8 * r)) & 255ull) * GATES + ((j >> 5) << 7) + o * 32 + (j & 31)];
                zq[r * 128 + j] = z;
            }
        }
        __syncthreads();

        const bool act = (m >> rr) & 1;
        if (tid < 256) {
            if (act) {
                const float* zp = zs + p * 4096 + rr * 128;
                float zi = zp[ii]      + zp[1024 + ii]      + zp[2048 + ii]      + zp[3072 + ii];
                float zf = zp[32 + ii] + zp[1024 + 32 + ii] + zp[2048 + 32 + ii] + zp[3072 + 32 + ii];
                float zg = zp[64 + ii] + zp[1024 + 64 + ii] + zp[2048 + 64 + ii] + zp[3072 + 64 + ii];
                float zo = zp[96 + ii] + zp[1024 + 96 + ii] + zp[2048 + 96 + ii] + zp[3072 + 96 + ii];
                float cn = sigm(zf) * c1 + sigm(zi) * tanhf(zg); c1 = cn;
                h1cur = sigm(zo) * tanhf(cn);
            }
#pragma unroll
            for (int rk = 0; rk < 4; rk++)
                cluster.map_shared_rank(h1b, rk)[pq * 1024 + rr * 128 + oc] = h1cur;
        }
        cluster.sync();

        {
            const float* hbase = (q < 2) ? (h1b + pq * 1024) : (h2b + p * 1024);
            const int koff = (q & 1) * 64;
            unsigned mm = (unsigned)m;
            while (mm) {
                int r = __ffs(mm) - 1; mm &= mm - 1;
                const float* hv = hbase + r * 128 + koff;
                float z = b2r;
#pragma unroll
                for (int kq = 0; kq < 16; kq++) {
                    float4 a4 = *(const float4*)(hv + kq * 4);
                    z = fmaf(a4.x, wtr[kq].x, z); z = fmaf(a4.y, wtr[kq].y, z);
                    z = fmaf(a4.z, wtr[kq].z, z); z = fmaf(a4.w, wtr[kq].w, z);
                }
                zq[r * 128 + j] = z;
            }
        }
        __syncthreads();

        if (tid < 256) {
            if (act) {
                const float* zp = zs + p * 4096 + rr * 128;
                float zi = zp[ii]      + zp[1024 + ii]      + zp[2048 + ii]      + zp[3072 + ii];
                float zf = zp[32 + ii] + zp[1024 + 32 + ii] + zp[2048 + 32 + ii] + zp[3072 + 32 + ii];
                float zg = zp[64 + ii] + zp[1024 + 64 + ii] + zp[2048 + 64 + ii] + zp[3072 + 64 + ii];
                float zo = zp[96 + ii] + zp[1024 + 96 + ii] + zp[2048 + 96 + ii] + zp[3072 + 96 + ii];
                float cn = sigm(zf) * c2 + sigm(zi) * tanhf(zg); c2 = cn;
                h2cur = sigm(zo) * tanhf(cn);
            }
#pragma unroll
            for (int rk = 0; rk < 4; rk++)
                cluster.map_shared_rank(h2b, rk)[pq * 1024 + rr * 128 + oc] = h2cur;
            g_sent[((size_t)bb * SEQ + t) * HID + oc] = h2cur;
        }
        p = pq;
    }
    cluster.sync();
}

__global__ void k_subject(const int* __restrict__ subj,
                          const float* __restrict__ betaW,const float* __restrict__ betab,
                          const float* __restrict__ gammaW,const float* __restrict__ gammab){
    __shared__ float sub[256];
    int b = blockIdx.x, tid = threadIdx.x;
    int s0 = subj[b*2+0], s1 = subj[b*2+1];
    if (tid < 128) sub[tid] = g_sent[((size_t)b*SEQ+s0)*HID + tid];
    else           sub[tid] = g_sent[((size_t)b*SEQ+s1)*HID + (tid-128)];
    __syncthreads();
    int col = tid & 127;
    const float* Wm = (tid < 128) ? betaW : gammaW;
    float a = (tid < 128) ? betab[col] : gammab[col];
    for (int k = 0; k < 256; k++) a = fmaf(sub[k], Wm[k*HID + col], a);
    if (tid < 128) g_beta [b*HID + col] = a;
    else           g_gamma[b*HID + col] = a;
}

// k_post v3: 32 rows per block (4 iterations) — weight staging amortized 4x
__global__ void __launch_bounds__(256) k_post(const float* __restrict__ poW,const float* __restrict__ pob,
                                              const float* __restrict__ subW,const float* __restrict__ subb,
                                              float* __restrict__ out){
    __shared__ float rowS[8][132];
    __shared__ float ctxS[8][132];
    __shared__ float poWs[128*20];   // 10240 B
    __shared__ float pobs[20];
    __shared__ float subWs[256];
    __shared__ float subbs[2];
    int tid=threadIdx.x;
    for (int i = tid; i < 128*20; i += 256) poWs[i] = poW[i];
    if (tid < 20)  pobs[tid]  = pob[tid];
    if (tid < 256) subWs[tid] = subW[tid];
    if (tid < 2)   subbs[tid] = subb[tid];
    __syncthreads();

    int warp=tid>>5, lane=tid&31;
#pragma unroll
    for (int it = 0; it < 4; it++) {
        size_t rid = (size_t)blockIdx.x * 32 + it * 8 + warp;   // b*512+t
        int b = (int)(rid >> 9);
        const float* row = g_sent + rid * HID;
        float x0=row[lane], x1=row[lane+32], x2=row[lane+64], x3=row[lane+96];
        float s=x0+x1+x2+x3, q=x0*x0+x1*x1+x2*x2+x3*x3;
#pragma unroll
        for(int d=16;d;d>>=1){ s+=__shfl_xor_sync(0xffffffffu,s,d); q+=__shfl_xor_sync(0xffffffffu,q,d); }
        float u=s*(1.f/128.f);
        float v=fmaxf(q*(1.f/128.f)-u*u,0.f);
        float inv=rsqrtf(v+1e-12f);
        const float* gma=g_gamma+b*HID; const float* bta=g_beta+b*HID;
        rowS[warp][lane]   =x0; ctxS[warp][lane]   =fmaf(gma[lane]   *inv,(x0-u),bta[lane]);
        rowS[warp][lane+32]=x1; ctxS[warp][lane+32]=fmaf(gma[lane+32]*inv,(x1-u),bta[lane+32]);
        rowS[warp][lane+64]=x2; ctxS[warp][lane+64]=fmaf(gma[lane+64]*inv,(x2-u),bta[lane+64]);
        rowS[warp][lane+96]=x3; ctxS[warp][lane+96]=fmaf(gma[lane+96]*inv,(x3-u),bta[lane+96]);
        __syncwarp();   // rowS/ctxS are warp-private
        if(lane<20){
            float a0=pobs[lane], a1=0.f, a2=0.f, a3=0.f;
#pragma unroll
            for(int k=0;k<128;k+=4){
                a0=fmaf(ctxS[warp][k  ],poWs[(k  )*20+lane],a0);
                a1=fmaf(ctxS[warp][k+1],poWs[(k+1)*20+lane],a1);
                a2=fmaf(ctxS[warp][k+2],poWs[(k+2)*20+lane],a2);
                a3=fmaf(ctxS[warp][k+3],poWs[(k+3)*20+lane],a3);
            }
            out[(size_t)BATCH*SEQ*2 + rid*20 + lane]=(a0+a1)+(a2+a3);
        }else if(lane<22){
            int c=lane-20;
            float a0=subbs[c], a1=0.f;
#pragma unroll
            for(int k=0;k<128;k+=2){
                a0=fmaf(rowS[warp][k  ],subWs[(k  )*2+c],a0);
                a1=fmaf(rowS[warp][k+1],subWs[(k+1)*2+c],a1);
            }
            out[rid*2+c]=a0+a1;
        }
        __syncwarp();   // protect rowS/ctxS reuse next iteration
    }
}

extern "C" void kernel_launch(void* const* d_in, const int* in_sizes, int n_in,
                              void* d_out, int out_size){
    const int*   char_ids=(const int*)d_in[0];
    const int*   word_ids=(const int*)d_in[1];
    const int*   subj    =(const int*)d_in[2];
    const float* emb_char=(const float*)d_in[3];
    const float* emb_word=(const float*)d_in[4];
    const float* Wwc     =(const float*)d_in[5];
    const float* bwc     =(const float*)d_in[6];
    const float* l1_Wx   =(const float*)d_in[7];
    const float* l1_Wh   =(const float*)d_in[8];
    const float* l1_b    =(const float*)d_in[9];
    const float* l2_Wx   =(const float*)d_in[10];
    const float* l2_Wh   =(const float*)d_in[11];
    const float* l2_b    =(const float*)d_in[12];
    const float* beta_W  =(const float*)d_in[13];
    const float* beta_b  =(const float*)d_in[14];
    const float* gamma_W =(const float*)d_in[15];
    const float* gamma_b =(const float*)d_in[16];
    const float* sub_W   =(const float*)d_in[17];
    const float* sub_b   =(const float*)d_in[18];
    const float* po_W    =(const float*)d_in[19];
    const float* po_b    =(const float*)d_in[20];
    float* out=(float*)d_out;

    const int smem_bytes = SMEM_FLOATS * 4; // 214016
    cudaFuncSetAttribute(k_lstm, cudaFuncAttributeMaxDynamicSharedMemorySize, smem_bytes);

    dim3 tgrid(SEQ/32, BATCH/32);
    k_trans<<<tgrid,256>>>(char_ids,word_ids);
    k_table<<<100,512>>>(emb_char,emb_word,Wwc,bwc,l1_Wx,l1_b);
    k_dummy<<<1,32>>>();   // shifts ncu -s 5 capture slot onto k_lstm
    k_lstm<<<128,512,smem_bytes>>>(l1_Wh,l2_Wx,l2_Wh,l2_b);
    k_subject<<<BATCH,256>>>(subj,beta_W,beta_b,gamma_W,gamma_b);
    k_post<<<(BATCH*SEQ)/32,256>>>(po_W,po_b,sub_W,sub_b,out);
}